// round 4
// baseline (speedup 1.0000x reference)
#include <cuda_runtime.h>

#define NEG (-1e30f)
#define LOG2E 1.4426950408889634f
#define LN2   0.6931471805599453f

constexpr int B  = 8;
constexpr int T  = 200;
constexpr int U1 = 101;
constexpr int V  = 512;
constexpr int U  = U1 - 1;
constexpr int D  = T + U1 - 1;           // 300 anti-diagonals
constexpr int NCELL = B * T * U1;        // 161600
constexpr int SB = 102;                  // smem row stride: lane stride 1-SB ≡ 27 mod 32, conflict-free

// Unskewed log2-prob tables: [b][t][u]  (pre-scaled by log2(e))
__device__ float g_blank[B * T * U1];
__device__ float g_emit [B * T * U];
__device__ float g_loss [B];

// logaddexp in log2 domain: no FMULs, raw EX2/LG2
__device__ __forceinline__ float logaddexp2_(float a, float b) {
    float mx = fmaxf(a, b);
    float mn = fminf(a, b);
    return mx + __log2f(1.0f + exp2f(mn - mx));
}

// One warp per (b,t,u) cell: logsumexp over V=512, emit blank/label log2-probs.
__global__ void __launch_bounds__(256) k_lse(const float* __restrict__ logits,
                                             const int*   __restrict__ targets) {
    int gw   = (blockIdx.x * blockDim.x + threadIdx.x) >> 5;
    int lane = threadIdx.x & 31;
    if (gw >= NCELL) return;

    int u = gw % U1;
    int t = (gw / U1) % T;
    int b = gw / (U1 * T);

    const float4* p = reinterpret_cast<const float4*>(logits) + (size_t)gw * (V / 4);
    float4 v0 = p[lane];
    float4 v1 = p[lane + 32];
    float4 v2 = p[lane + 64];
    float4 v3 = p[lane + 96];

    float m = fmaxf(fmaxf(fmaxf(v0.x, v0.y), fmaxf(v0.z, v0.w)),
                    fmaxf(fmaxf(fmaxf(v1.x, v1.y), fmaxf(v1.z, v1.w)),
                          fmaxf(fmaxf(fmaxf(v2.x, v2.y), fmaxf(v2.z, v2.w)),
                                fmaxf(fmaxf(v3.x, v3.y), fmaxf(v3.z, v3.w)))));
#pragma unroll
    for (int o = 16; o; o >>= 1) m = fmaxf(m, __shfl_xor_sync(0xffffffffu, m, o));

    float s = __expf(v0.x - m) + __expf(v0.y - m) + __expf(v0.z - m) + __expf(v0.w - m)
            + __expf(v1.x - m) + __expf(v1.y - m) + __expf(v1.z - m) + __expf(v1.w - m)
            + __expf(v2.x - m) + __expf(v2.y - m) + __expf(v2.z - m) + __expf(v2.w - m)
            + __expf(v3.x - m) + __expf(v3.y - m) + __expf(v3.z - m) + __expf(v3.w - m);
#pragma unroll
    for (int o = 16; o; o >>= 1) s += __shfl_xor_sync(0xffffffffu, s, o);

    float lse = m + __logf(s);

    // blank = vocab index 0, owned by lane 0 (v0.x). Store in log2 units.
    if (lane == 0) g_blank[(size_t)b * T * U1 + t * U1 + u] = (v0.x - lse) * LOG2E;

    // emit = vocab index targets[b, u+1]  (only defined for u < U)
    int lab = (u < U) ? targets[b * U1 + u + 1] : -1;
    if (lab >= 0) {
        int chunk = lab >> 2;            // which float4 (0..127)
        if ((chunk & 31) == lane) {
            int j = chunk >> 5, c = lab & 3;
            float4 vv = (j == 0) ? v0 : (j == 1) ? v1 : (j == 2) ? v2 : v3;
            float ev  = (c == 0) ? vv.x : (c == 1) ? vv.y : (c == 2) ? vv.z : vv.w;
            g_emit[(size_t)b * T * U + t * U + u] = (ev - lse) * LOG2E;
        }
    }
}

// Barrier-free anti-diagonal alpha DP: one CTA per batch, warp 0 owns the row.
// Lane i holds cells u = i + 32j, j = 0..3. P[u-1] via one rotating shfl per step.
constexpr int SMEM_DP = 2 * T * SB * (int)sizeof(float);

__global__ void __launch_bounds__(256) k_dp(const int* __restrict__ fbank_len,
                                            const int* __restrict__ text_len) {
    extern __shared__ float sm[];
    float* smb = sm;                 // blank [T][SB]
    float* sme = sm + T * SB;        // emit  [T][SB]

    int b   = blockIdx.x;
    int tid = threadIdx.x;

    const float* gb = g_blank + (size_t)b * T * U1;
    const float* ge = g_emit  + (size_t)b * T * U;

    // Stage tables into smem (coalesced global reads; padded smem rows)
    for (int i = tid; i < T * U1; i += 256) smb[(i / U1) * SB + (i % U1)] = gb[i];
    for (int i = tid; i < T * U;  i += 256) sme[(i / U)  * SB + (i % U)]  = ge[i];
    __syncthreads();
    if (tid >= 32) return;           // warps 1..7 retire; warp 0 runs the DP

    int lane    = tid;
    int lab_len = text_len[b] - 1;
    int tfin    = fbank_len[b] - 1;
    int dfin    = tfin + lab_len;
    int src     = (lane + 31) & 31;  // rotate-left source for shfl

    // p[j] = alpha at u = lane + 32j (log2 domain)
    float p0 = (lane == 0) ? 0.0f : NEG;
    float p1 = NEG, p2 = NEG, p3 = NEG;
    float afin = NEG;

#pragma unroll 2
    for (int d = 1; d < D; ++d) {
        // P[u-1]: lane i gets lane i-1's same cell; lane 0 wraps to lane 31's previous cell
        float s0 = __shfl_sync(0xffffffffu, p0, src);
        float s1 = __shfl_sync(0xffffffffu, p1, src);
        float s2 = __shfl_sync(0xffffffffu, p2, src);
        float s3 = __shfl_sync(0xffffffffu, p3, src);
        float q0 = (lane == 0) ? NEG : s0;   // u=0 has no predecessor
        float q1 = (lane == 0) ? s0 : s1;    // lane0 u=32: pred = lane31 cell0 (u=31)
        float q2 = (lane == 0) ? s1 : s2;
        float q3 = (lane == 0) ? s2 : s3;

#pragma unroll
        for (int j = 0; j < 4; ++j) {
            int u = lane + 32 * j;
            float pj = (j == 0) ? p0 : (j == 1) ? p1 : (j == 2) ? p2 : p3;
            float qj = (j == 0) ? q0 : (j == 1) ? q1 : (j == 2) ? q2 : q3;
            int t = d - u;
            float nv = NEG;
            if (u < U1 && t >= 0 && t < T) {
                float stay = (t >= 1) ? pj + smb[(t - 1) * SB + u] : NEG;
                float mv   = (u >= 1) ? qj + sme[t * SB + (u - 1)] : NEG;
                nv = logaddexp2_(stay, mv);
                if (d == dfin && u == lab_len) afin = nv;
            }
            if (j == 0) p0 = nv; else if (j == 1) p1 = nv; else if (j == 2) p2 = nv; else p3 = nv;
        }
    }

    if (lane == (lab_len & 31))
        g_loss[b] = -LN2 * (afin + smb[tfin * SB + lab_len]);
}

__global__ void k_mean(float* __restrict__ out) {
    float s = 0.0f;
#pragma unroll
    for (int i = 0; i < B; ++i) s += g_loss[i];
    *out = s / (float)B;
}

extern "C" void kernel_launch(void* const* d_in, const int* in_sizes, int n_in,
                              void* d_out, int out_size) {
    const float* logits  = (const float*)d_in[0];
    const int*   targets = (const int*)d_in[1];
    const int*   fb      = (const int*)d_in[2];
    const int*   tl      = (const int*)d_in[3];

    cudaFuncSetAttribute(k_dp, cudaFuncAttributeMaxDynamicSharedMemorySize, SMEM_DP);

    int blocks = (NCELL * 32 + 255) / 256;  // one warp per cell, 8 warps/block
    k_lse<<<blocks, 256>>>(logits, targets);
    k_dp<<<B, 256, SMEM_DP>>>(fb, tl);
    k_mean<<<1, 1>>>((float*)d_out);
}

// round 5
// speedup vs baseline: 1.3166x; 1.3166x over previous
#include <cuda_runtime.h>

#define NEG (-1e30f)
#define LOG2E 1.4426950408889634f
#define LN2   0.6931471805599453f

constexpr int B  = 8;
constexpr int T  = 200;
constexpr int U1 = 101;
constexpr int V  = 512;
constexpr int U  = U1 - 1;
constexpr int D  = T + U1 - 1;           // 300 anti-diagonals
constexpr int NCELL = B * T * U1;        // 161600
constexpr int SB = 102;                  // smem row stride

// Unskewed log2-prob tables: [b][t][u]  (pre-scaled by log2 e)
__device__ float g_blank[B * T * U1];
__device__ float g_emit [B * T * U];
__device__ float g_loss [B];

// logaddexp in log2 domain
__device__ __forceinline__ float laddexp2(float a, float b) {
    float mx = fmaxf(a, b);
    float dd = -fabsf(a - b);
    return mx + __log2f(1.0f + exp2f(dd));
}

// One warp per (b,t,u) cell: logsumexp over V=512. Cells outside the
// (fbank_len, text_len) region are never consumed by the DP -> skip them.
__global__ void __launch_bounds__(256) k_lse(const float* __restrict__ logits,
                                             const int*   __restrict__ targets,
                                             const int*   __restrict__ fbank_len,
                                             const int*   __restrict__ text_len) {
    int gw   = (blockIdx.x * blockDim.x + threadIdx.x) >> 5;
    int lane = threadIdx.x & 31;
    if (gw >= NCELL) return;

    int u = gw % U1;
    int t = (gw / U1) % T;
    int b = gw / (U1 * T);

    int lab_len = text_len[b] - 1;
    if (t >= fbank_len[b] || u > lab_len) return;   // dead cell: skip 2KB of logits

    const float4* p = reinterpret_cast<const float4*>(logits) + (size_t)gw * (V / 4);
    float4 v0 = p[lane];
    float4 v1 = p[lane + 32];
    float4 v2 = p[lane + 64];
    float4 v3 = p[lane + 96];

    float m = fmaxf(fmaxf(fmaxf(v0.x, v0.y), fmaxf(v0.z, v0.w)),
                    fmaxf(fmaxf(fmaxf(v1.x, v1.y), fmaxf(v1.z, v1.w)),
                          fmaxf(fmaxf(fmaxf(v2.x, v2.y), fmaxf(v2.z, v2.w)),
                                fmaxf(fmaxf(v3.x, v3.y), fmaxf(v3.z, v3.w)))));
#pragma unroll
    for (int o = 16; o; o >>= 1) m = fmaxf(m, __shfl_xor_sync(0xffffffffu, m, o));

    float s = __expf(v0.x - m) + __expf(v0.y - m) + __expf(v0.z - m) + __expf(v0.w - m)
            + __expf(v1.x - m) + __expf(v1.y - m) + __expf(v1.z - m) + __expf(v1.w - m)
            + __expf(v2.x - m) + __expf(v2.y - m) + __expf(v2.z - m) + __expf(v2.w - m)
            + __expf(v3.x - m) + __expf(v3.y - m) + __expf(v3.z - m) + __expf(v3.w - m);
#pragma unroll
    for (int o = 16; o; o >>= 1) s += __shfl_xor_sync(0xffffffffu, s, o);

    float lse = m + __logf(s);

    if (lane == 0) g_blank[(size_t)b * T * U1 + t * U1 + u] = (v0.x - lse) * LOG2E;

    int lab = (u < U) ? targets[b * U1 + u + 1] : -1;
    if (lab >= 0) {
        int chunk = lab >> 2;
        if ((chunk & 31) == lane) {
            int j = chunk >> 5, c = lab & 3;
            float4 vv = (j == 0) ? v0 : (j == 1) ? v1 : (j == 2) ? v2 : v3;
            float ev  = (c == 0) ? vv.x : (c == 1) ? vv.y : (c == 2) ? vv.z : vv.w;
            g_emit[(size_t)b * T * U + t * U + u] = (ev - lse) * LOG2E;
        }
    }
}

// Anti-diagonal alpha DP: 1 CTA / batch, 128 threads, thread u owns alpha[.,u]
// in a register. P[u-1] via shfl_up (pre-barrier, latency hidden); warp
// boundaries via 3-slot double-buffered smem. Tables smem-resident.
constexpr int SMEM_DP = 2 * T * SB * (int)sizeof(float);

__global__ void __launch_bounds__(128) k_dp(const int* __restrict__ fbank_len,
                                            const int* __restrict__ text_len) {
    extern __shared__ float sm[];
    float* smb = sm;                 // blank [T][SB]
    float* sme = sm + T * SB;        // emit  [T][SB]
    __shared__ float bnd[2][4];      // warp-boundary alpha values, double-buffered

    int b    = blockIdx.x;
    int tid  = threadIdx.x;
    int lane = tid & 31;
    int w    = tid >> 5;
    int u    = tid;

    const float* gb = g_blank + (size_t)b * T * U1;
    const float* ge = g_emit  + (size_t)b * T * U;

    for (int i = tid; i < T * U1; i += 128) smb[(i / U1) * SB + (i % U1)] = gb[i];
    for (int i = tid; i < T * U;  i += 128) sme[(i / U)  * SB + (i % U)]  = ge[i];

    int lab_len = text_len[b] - 1;
    int tfin    = fbank_len[b] - 1;
    int dfin    = tfin + lab_len;
    bool fin    = (u == lab_len);
    __syncthreads();

    // my = alpha(t = d-1-u, u); pm = neighbor's alpha(t, u-1) for current step
    float my = (u == 0) ? 0.0f : NEG;
    float pm = (u == 1) ? 0.0f : NEG;
    float afin = NEG;

    int t = 1 - u;                               // t at d=1
    // prefetch blank/emit for d=1
    float cb = (t >= 1 && t < T)            ? smb[(t - 1) * SB + u]     : NEG;
    float ce = (t >= 0 && t < T && u >= 1)  ? sme[t * SB + (u - 1)]     : NEG;

    for (int d = 1; d < D; ++d, ++t) {
        bool cellv = (t >= 0) && (t < T) && (u < U1);
        float stay = (t >= 1 && t < T && u < U1) ? my + cb : NEG;   // pre-barrier computable
        float move = (cellv && u >= 1)           ? pm + ce : NEG;
        float nv   = cellv ? laddexp2(stay, move) : NEG;

        afin = (fin && d == dfin) ? nv : afin;

        // exchange alpha for next step
        float sh = __shfl_up_sync(0xffffffffu, nv, 1);
        if (lane == 31 && w < 3) bnd[d & 1][w] = nv;

        // prefetch blank/emit for d+1
        int tn = t + 1;
        cb = (tn >= 1 && tn < T)           ? smb[(tn - 1) * SB + u] : NEG;
        ce = (tn >= 0 && tn < T && u >= 1) ? sme[tn * SB + (u - 1)] : NEG;

        __syncthreads();
        pm = (lane == 0) ? ((w > 0) ? bnd[d & 1][w - 1] : NEG) : sh;
        my = nv;
    }

    if (fin)
        g_loss[b] = -LN2 * (afin + smb[tfin * SB + lab_len]);
}

__global__ void k_mean(float* __restrict__ out) {
    float s = 0.0f;
#pragma unroll
    for (int i = 0; i < B; ++i) s += g_loss[i];
    *out = s / (float)B;
}

extern "C" void kernel_launch(void* const* d_in, const int* in_sizes, int n_in,
                              void* d_out, int out_size) {
    const float* logits  = (const float*)d_in[0];
    const int*   targets = (const int*)d_in[1];
    const int*   fb      = (const int*)d_in[2];
    const int*   tl      = (const int*)d_in[3];

    cudaFuncSetAttribute(k_dp, cudaFuncAttributeMaxDynamicSharedMemorySize, SMEM_DP);

    int blocks = (NCELL * 32 + 255) / 256;  // one warp per cell
    k_lse<<<blocks, 256>>>(logits, targets, fb, tl);
    k_dp<<<B, 128, SMEM_DP>>>(fb, tl);
    k_mean<<<1, 1>>>((float*)d_out);
}